// round 9
// baseline (speedup 1.0000x reference)
#include <cuda_runtime.h>
#include <cstdint>

// ---- problem constants ----
#define NODES     4096
#define T_HIST    24
#define D_SKIP    256
#define E_END     128
#define KW        13
#define F_STEPS   12
#define OUT_DIM   2
#define NPB       5
#define NTHREADS  256
#define MAXCTA    832

// ---- smem layout (floats) ----
// mainloop: xs [128][68] @0 (one 64-k quarter), w1s 2 bufs x [128][36] @8704 (ends 17920)
// stage 2 : hs [120][128] @0 (ends 15360), w2s [13][257] @15360 (ends 18701), red @18701
#define XS_OFF     0
#define XS_STRIDE  68
#define W1S_OFF    8704
#define W1S_BUF    4608
#define W1S_STRIDE 36
#define HS_OFF     0
#define HS_STRIDE  128
#define W2S_OFF    15360
#define W2S_STRIDE 257
#define RED_OFF    18701
#define SMEM_FLOATS 19181
#define SMEM_BYTES  (SMEM_FLOATS * 4)

// ---- device scratch ----
__device__ int d_perm[NODES];
__device__ int d_cta_expert[MAXCTA];
__device__ int d_cta_base[MAXCTA];
__device__ int d_cta_cnt[MAXCTA];
__device__ int d_num_ctas;
__device__ float d_w1tf[8 * E_END * D_SKIP];      // tf32-preconverted W1
__device__ float d_w2t[8 * KW * OUT_DIM * E_END]; // W2 transposed to [e][kk][o*128+en]

__device__ __forceinline__ float tf32_rna(float x) {
    unsigned u;
    asm("cvt.rna.tf32.f32 %0, %1;" : "=r"(u) : "f"(x));
    return __uint_as_float(u);
}

__device__ __forceinline__ void cp16(uint32_t dst, const float* src) {
    asm volatile("cp.async.ca.shared.global [%0], [%1], 16;" :: "r"(dst), "l"(src));
}

__device__ __forceinline__ void mma_tf32(float (&d)[4], const unsigned (&a)[4],
                                         unsigned b0, unsigned b1) {
    asm volatile(
        "mma.sync.aligned.m16n8k8.row.col.f32.tf32.tf32.f32 "
        "{%0,%1,%2,%3}, {%4,%5,%6,%7}, {%8,%9}, {%0,%1,%2,%3};"
        : "+f"(d[0]), "+f"(d[1]), "+f"(d[2]), "+f"(d[3])
        : "r"(a[0]), "r"(a[1]), "r"(a[2]), "r"(a[3]), "r"(b0), "r"(b1));
}

// ================= prepass: parallel bucket + table build =================
__global__ void prepass_kernel(const int* __restrict__ labels) {
    __shared__ int cnt[8], off[8], pos[8], blkoff[9], total_s;
    const int tid = threadIdx.x;
    const int lane = tid & 31;
    if (tid < 8) { cnt[tid] = 0; pos[tid] = 0; }
    __syncthreads();
    for (int i = tid; i < NODES; i += 512) {
        int l = labels[i];
        unsigned mask = __match_any_sync(0xffffffffu, l);
        int leader = __ffs(mask) - 1;
        if (lane == leader) atomicAdd(&cnt[l], __popc(mask));
    }
    __syncthreads();
    if (tid == 0) {
        int acc = 0, bacc = 0;
        for (int e = 0; e < 8; ++e) {
            off[e] = acc;
            blkoff[e] = bacc;
            acc += cnt[e];
            bacc += (cnt[e] + NPB - 1) / NPB;
        }
        blkoff[8] = bacc;
        total_s = bacc;
        d_num_ctas = bacc;
    }
    __syncthreads();
    for (int i = tid; i < NODES; i += 512) {
        int l = labels[i];
        unsigned mask = __match_any_sync(0xffffffffu, l);
        int leader = __ffs(mask) - 1;
        int rank = __popc(mask & ((1u << lane) - 1u));
        int basep = 0;
        if (lane == leader) basep = atomicAdd(&pos[l], __popc(mask));
        basep = __shfl_sync(0xffffffffu, basep, leader);
        d_perm[off[l] + basep + rank] = i;
    }
    const int total = total_s;
    for (int i = tid; i < total; i += 512) {
        int e = 0;
        while (blkoff[e + 1] <= i) ++e;
        int j = i - blkoff[e];
        int rem = cnt[e] - j * NPB;
        d_cta_expert[i] = e;
        d_cta_base[i]   = off[e] + j * NPB;
        d_cta_cnt[i]    = rem < NPB ? rem : NPB;
    }
}

// ================= convert: W1 -> tf32 copy, W2 -> transposed layout =================
__global__ void convert_kernel(const float* __restrict__ W1, const float* __restrict__ W2) {
    const int idx = blockIdx.x * blockDim.x + threadIdx.x;
    const int stride = gridDim.x * blockDim.x;
    for (int i = idx; i < 8 * E_END * D_SKIP; i += stride)
        d_w1tf[i] = tf32_rna(W1[i]);
    for (int i = idx; i < 8 * KW * OUT_DIM * E_END; i += stride) {
        int e  = i / (KW * OUT_DIM * E_END);
        int r  = i - e * (KW * OUT_DIM * E_END);
        int kk = r >> 8;
        int oe = r & 255;
        int o  = oe >> 7;
        int en = oe & 127;
        d_w2t[i] = W2[((e * OUT_DIM + o) * E_END + en) * KW + kk];
    }
}

// ================= main kernel =================
__global__ void __launch_bounds__(NTHREADS, 3)
tcnn_grouped_kernel(const float* __restrict__ x,
                    const float* __restrict__ b1,
                    const float* __restrict__ b2,
                    float* __restrict__ out)
{
    extern __shared__ __align__(16) float sm[];
    const int bid = blockIdx.x;
    if (bid >= d_num_ctas) return;

    const int expert = d_cta_expert[bid];
    const int nbase  = d_cta_base[bid];
    const int nm     = d_cta_cnt[bid];

    const int tid  = threadIdx.x;
    const int warp = tid >> 5;
    const int lane = tid & 31;
    const int g    = lane >> 2;
    const int tig  = lane & 3;
    const int wm   = warp & 1;       // 0..1 : e-half
    const int wn   = warp >> 1;      // 0..3 : row-quarter

    // per-node x base pointers
    const float* pxn[NPB];
    #pragma unroll
    for (int s = 0; s < NPB; ++s) {
        int node = (s < nm) ? d_perm[nbase + s] : d_perm[nbase];
        pxn[s] = x + (size_t)node * (T_HIST * D_SKIP);
    }

    // ---- W1 cp.async setup ----
    const int pe = tid >> 3;      // 0..31 (row group base)
    const int pk = tid & 7;       // 0..7  (16B quad)
    const float* w1src = d_w1tf + (size_t)expert * (E_END * D_SKIP) + pk * 4;  // + row*256 + c*32
    const uint32_t w1s_saddr = (uint32_t)__cvta_generic_to_shared(sm + W1S_OFF) + pk * 16;

    // prologue: chunk 0 -> buf 0
    #pragma unroll
    for (int j = 0; j < 4; ++j) {
        const int row = pe + 32 * j;
        cp16(w1s_saddr + row * (W1S_STRIDE * 4), w1src + row * D_SKIP);
    }
    asm volatile("cp.async.commit_group;");

    // ---- mainloop: D[e][row] = sum_k W1[e][k]*relu(x)[row][k] (tf32 mma) ----
    float acc[4][4][4];
    #pragma unroll
    for (int mt = 0; mt < 4; ++mt)
        #pragma unroll
        for (int nt = 0; nt < 4; ++nt)
            #pragma unroll
            for (int i = 0; i < 4; ++i) acc[mt][nt][i] = 0.f;

    #pragma unroll 1
    for (int c = 0; c < 8; ++c) {
        const int buf = c & 1;
        if ((c & 1) == 0) {
            __syncthreads();   // xs consumed; also guards w1s[(c+1)&1] (mma c-1 done)
            const int kbase = (c >> 1) * 64;
            #pragma unroll 1
            for (int s = 0; s < nm; ++s) {
                const float* xg = pxn[s] + kbase;
                #pragma unroll
                for (int i = tid; i < T_HIST * 16; i += NTHREADS) {
                    int t  = i >> 4;
                    int kq = i & 15;
                    float4 v = *(const float4*)(xg + t * D_SKIP + kq * 4);
                    v.x = tf32_rna(fmaxf(v.x, 0.f));
                    v.y = tf32_rna(fmaxf(v.y, 0.f));
                    v.z = tf32_rna(fmaxf(v.z, 0.f));
                    v.w = tf32_rna(fmaxf(v.w, 0.f));
                    *(float4*)(sm + XS_OFF + (s * T_HIST + t) * XS_STRIDE + kq * 4) = v;
                }
            }
        } else {
            __syncthreads();   // mma c-1 done -> w1s[(c+1)&1] free for prefetch
        }

        if (c < 7) {
            const int nb = (c + 1) & 1;
            const float* src = w1src + (c + 1) * 32;
            const uint32_t dst = w1s_saddr + nb * (W1S_BUF * 4);
            #pragma unroll
            for (int j = 0; j < 4; ++j) {
                const int row = pe + 32 * j;
                cp16(dst + row * (W1S_STRIDE * 4), src + row * D_SKIP);
            }
            asm volatile("cp.async.commit_group;");
            asm volatile("cp.async.wait_group 1;");
        } else {
            asm volatile("cp.async.wait_group 0;");
        }
        __syncthreads();       // chunk c's w1s + xs visible to all

        const float* w1b = sm + W1S_OFF + buf * W1S_BUF;
        #pragma unroll
        for (int kt = 0; kt < 4; ++kt) {
            const int kb = kt * 8;                 // k within chunk (w1s)
            const int xk = (c & 1) * 32 + kb;      // k within quarter (xs)
            unsigned a[4][4];
            #pragma unroll
            for (int mt = 0; mt < 4; ++mt) {
                const int e0 = wm * 64 + mt * 16 + g;
                a[mt][0] = __float_as_uint(w1b[e0 * W1S_STRIDE + kb + tig]);
                a[mt][1] = __float_as_uint(w1b[(e0 + 8) * W1S_STRIDE + kb + tig]);
                a[mt][2] = __float_as_uint(w1b[e0 * W1S_STRIDE + kb + tig + 4]);
                a[mt][3] = __float_as_uint(w1b[(e0 + 8) * W1S_STRIDE + kb + tig + 4]);
            }
            #pragma unroll
            for (int nt = 0; nt < 4; ++nt) {
                const int col = wn * 32 + nt * 8 + g;   // row index
                unsigned b0  = __float_as_uint(sm[XS_OFF + col * XS_STRIDE + xk + tig]);
                unsigned b1v = __float_as_uint(sm[XS_OFF + col * XS_STRIDE + xk + tig + 4]);
                #pragma unroll
                for (int mt = 0; mt < 4; ++mt)
                    mma_tf32(acc[mt][nt], a[mt], b0, b1v);
            }
        }
    }

    __syncthreads();   // all xs/w1s reads done -> reuse as hs[row][e]

    // ---- stage-2 weights: contiguous copy from pre-transposed d_w2t ----
    {
        const float* w2g = d_w2t + expert * (KW * OUT_DIM * E_END);
        #pragma unroll
        for (int i = tid; i < KW * OUT_DIM * E_END; i += NTHREADS)
            sm[W2S_OFF + (i >> 8) * W2S_STRIDE + (i & 255)] = w2g[i];
    }

    // ---- epilogue: hs[row][e] = relu(D[e][row] + b1[e]) ----
    const float* b1g = b1 + expert * E_END;
    const int maxrow = nm * T_HIST;
    #pragma unroll
    for (int mt = 0; mt < 4; ++mt) {
        const int eA = wm * 64 + mt * 16 + g;
        const int eB = eA + 8;
        const float bA = b1g[eA];
        const float bB = b1g[eB];
        #pragma unroll
        for (int nt = 0; nt < 4; ++nt) {
            const int row0 = wn * 32 + nt * 8 + 2 * tig;
            if (row0 < maxrow) {
                sm[HS_OFF + row0 * HS_STRIDE + eA] = fmaxf(acc[mt][nt][0] + bA, 0.f);
                sm[HS_OFF + row0 * HS_STRIDE + eB] = fmaxf(acc[mt][nt][2] + bB, 0.f);
            }
            const int row1 = row0 + 1;
            if (row1 < maxrow) {
                sm[HS_OFF + row1 * HS_STRIDE + eA] = fmaxf(acc[mt][nt][1] + bA, 0.f);
                sm[HS_OFF + row1 * HS_STRIDE + eB] = fmaxf(acc[mt][nt][3] + bB, 0.f);
            }
        }
    }
    __syncthreads();

    // ---- stage 2: per-node temporal conv, register resident ----
    #pragma unroll 1
    for (int iter = 0; iter < 3; ++iter) {
        const int wj   = iter * 8 + warp;
        const int node = wj >> 2;
        const int w4   = wj & 3;
        if (node < nm) {
            const int e = w4 * 32 + lane;
            float w2r[OUT_DIM][KW];
            #pragma unroll
            for (int o = 0; o < OUT_DIM; ++o)
                #pragma unroll
                for (int kk = 0; kk < KW; ++kk)
                    w2r[o][kk] = sm[W2S_OFF + kk * W2S_STRIDE + o * E_END + e];

            float a2[F_STEPS][OUT_DIM];
            #pragma unroll
            for (int f = 0; f < F_STEPS; ++f) { a2[f][0] = 0.f; a2[f][1] = 0.f; }

            const float* hsp = sm + HS_OFF + node * T_HIST * HS_STRIDE + e;
            #pragma unroll
            for (int t = 0; t < T_HIST; ++t) {
                const float hv = hsp[t * HS_STRIDE];
                #pragma unroll
                for (int kk = 0; kk < KW; ++kk) {
                    const int f = t - kk;
                    if (f >= 0 && f < F_STEPS) {
                        a2[f][0] = fmaf(hv, w2r[0][kk], a2[f][0]);
                        a2[f][1] = fmaf(hv, w2r[1][kk], a2[f][1]);
                    }
                }
            }
            #pragma unroll
            for (int f = 0; f < F_STEPS; ++f)
                #pragma unroll
                for (int o = 0; o < OUT_DIM; ++o) {
                    float v = a2[f][o];
                    v += __shfl_xor_sync(0xffffffffu, v, 16);
                    v += __shfl_xor_sync(0xffffffffu, v, 8);
                    v += __shfl_xor_sync(0xffffffffu, v, 4);
                    v += __shfl_xor_sync(0xffffffffu, v, 2);
                    v += __shfl_xor_sync(0xffffffffu, v, 1);
                    a2[f][o] = v;
                }
            if (lane == 0) {
                #pragma unroll
                for (int f = 0; f < F_STEPS; ++f) {
                    sm[RED_OFF + (node * 4 + w4) * 24 + f * 2 + 0] = a2[f][0];
                    sm[RED_OFF + (node * 4 + w4) * 24 + f * 2 + 1] = a2[f][1];
                }
            }
        }
    }
    __syncthreads();

    if (tid < nm * (F_STEPS * OUT_DIM)) {
        const int node = tid / 24;
        const int fo   = tid - node * 24;
        float ssum = sm[RED_OFF + (node * 4 + 0) * 24 + fo]
                   + sm[RED_OFF + (node * 4 + 1) * 24 + fo]
                   + sm[RED_OFF + (node * 4 + 2) * 24 + fo]
                   + sm[RED_OFF + (node * 4 + 3) * 24 + fo];
        ssum += b2[expert * OUT_DIM + (fo & 1)];
        out[(size_t)d_perm[nbase + node] * (F_STEPS * OUT_DIM) + fo] = ssum;
    }
}

extern "C" void kernel_launch(void* const* d_in, const int* in_sizes, int n_in,
                              void* d_out, int out_size) {
    const float* x      = (const float*)d_in[0];
    const int*   labels = (const int*)d_in[1];
    const float* W1     = (const float*)d_in[2];
    const float* b1     = (const float*)d_in[3];
    const float* W2     = (const float*)d_in[4];
    const float* b2     = (const float*)d_in[5];
    float* out = (float*)d_out;

    static bool attr_set = false;
    if (!attr_set) {
        cudaFuncSetAttribute(tcnn_grouped_kernel,
                             cudaFuncAttributeMaxDynamicSharedMemorySize, SMEM_BYTES);
        attr_set = true;
    }

    prepass_kernel<<<1, 512>>>(labels);
    convert_kernel<<<512, 256>>>(W1, W2);
    tcnn_grouped_kernel<<<MAXCTA, NTHREADS, SMEM_BYTES>>>(x, b1, b2, out);
}

// round 10
// speedup vs baseline: 1.3021x; 1.3021x over previous
#include <cuda_runtime.h>
#include <cstdint>

// ---- problem constants ----
#define NODES     4096
#define T_HIST    24
#define D_SKIP    256
#define E_END     128
#define KW        13
#define F_STEPS   12
#define OUT_DIM   2
#define NPB       5
#define NTHREADS  256
#define MAXCTA    832

// ---- smem layout (floats), occupancy-2 budget ----
// mainloop: xs [128][132] @0 (one 128-k half), w1s 2 bufs x [128][36] @16896 (ends 26112)
// stage 2 : hs [120][128] @0 (ends 15360), w2s [13][257] @15360 (ends 18701), red @18701
#define XS_OFF     0
#define XS_STRIDE  132
#define W1S_OFF    16896
#define W1S_BUF    4608
#define W1S_STRIDE 36
#define HS_OFF     0
#define HS_STRIDE  128
#define W2S_OFF    15360
#define W2S_STRIDE 257
#define RED_OFF    18701
#define SMEM_FLOATS 26112
#define SMEM_BYTES  (SMEM_FLOATS * 4)

// ---- device scratch ----
__device__ int d_perm[NODES];
__device__ int d_cta_expert[MAXCTA];
__device__ int d_cta_base[MAXCTA];
__device__ int d_cta_cnt[MAXCTA];
__device__ int d_num_ctas;
__device__ float d_w1tf[8 * E_END * D_SKIP];      // tf32-preconverted W1
__device__ float d_w2t[8 * KW * OUT_DIM * E_END]; // W2 transposed to [e][kk][o*128+en]

__device__ __forceinline__ float tf32_rna(float x) {
    unsigned u;
    asm("cvt.rna.tf32.f32 %0, %1;" : "=r"(u) : "f"(x));
    return __uint_as_float(u);
}

__device__ __forceinline__ void cp16(uint32_t dst, const float* src) {
    asm volatile("cp.async.ca.shared.global [%0], [%1], 16;" :: "r"(dst), "l"(src));
}

__device__ __forceinline__ void mma_tf32(float (&d)[4], const unsigned (&a)[4],
                                         unsigned b0, unsigned b1) {
    asm volatile(
        "mma.sync.aligned.m16n8k8.row.col.f32.tf32.tf32.f32 "
        "{%0,%1,%2,%3}, {%4,%5,%6,%7}, {%8,%9}, {%0,%1,%2,%3};"
        : "+f"(d[0]), "+f"(d[1]), "+f"(d[2]), "+f"(d[3])
        : "r"(a[0]), "r"(a[1]), "r"(a[2]), "r"(a[3]), "r"(b0), "r"(b1));
}

// ================= setup: block 0 = prepass, blocks 1.. = weight convert =================
__global__ void setup_kernel(const int* __restrict__ labels,
                             const float* __restrict__ W1,
                             const float* __restrict__ W2) {
    if (blockIdx.x == 0) {
        __shared__ int cnt[8], off[8], pos[8], blkoff[9], total_s;
        const int tid = threadIdx.x;
        const int lane = tid & 31;
        if (tid < 8) { cnt[tid] = 0; pos[tid] = 0; }
        __syncthreads();
        for (int i = tid; i < NODES; i += NTHREADS) {
            int l = labels[i];
            unsigned mask = __match_any_sync(0xffffffffu, l);
            int leader = __ffs(mask) - 1;
            if (lane == leader) atomicAdd(&cnt[l], __popc(mask));
        }
        __syncthreads();
        if (tid == 0) {
            int acc = 0, bacc = 0;
            for (int e = 0; e < 8; ++e) {
                off[e] = acc;
                blkoff[e] = bacc;
                acc += cnt[e];
                bacc += (cnt[e] + NPB - 1) / NPB;
            }
            blkoff[8] = bacc;
            total_s = bacc;
            d_num_ctas = bacc;
        }
        __syncthreads();
        for (int i = tid; i < NODES; i += NTHREADS) {
            int l = labels[i];
            unsigned mask = __match_any_sync(0xffffffffu, l);
            int leader = __ffs(mask) - 1;
            int rank = __popc(mask & ((1u << lane) - 1u));
            int basep = 0;
            if (lane == leader) basep = atomicAdd(&pos[l], __popc(mask));
            basep = __shfl_sync(0xffffffffu, basep, leader);
            d_perm[off[l] + basep + rank] = i;
        }
        const int total = total_s;
        for (int i = tid; i < total; i += NTHREADS) {
            int e = 0;
            while (blkoff[e + 1] <= i) ++e;
            int j = i - blkoff[e];
            int rem = cnt[e] - j * NPB;
            d_cta_expert[i] = e;
            d_cta_base[i]   = off[e] + j * NPB;
            d_cta_cnt[i]    = rem < NPB ? rem : NPB;
        }
    } else {
        const int idx = (blockIdx.x - 1) * NTHREADS + threadIdx.x;
        const int stride = (gridDim.x - 1) * NTHREADS;
        for (int i = idx; i < 8 * E_END * D_SKIP; i += stride)
            d_w1tf[i] = tf32_rna(W1[i]);
        for (int i = idx; i < 8 * KW * OUT_DIM * E_END; i += stride) {
            int e  = i / (KW * OUT_DIM * E_END);
            int r  = i - e * (KW * OUT_DIM * E_END);
            int kk = r >> 8;
            int oe = r & 255;
            int o  = oe >> 7;
            int en = oe & 127;
            d_w2t[i] = W2[((e * OUT_DIM + o) * E_END + en) * KW + kk];
        }
    }
}

// ================= main kernel =================
__global__ void __launch_bounds__(NTHREADS, 2)
tcnn_grouped_kernel(const float* __restrict__ x,
                    const float* __restrict__ b1,
                    const float* __restrict__ b2,
                    float* __restrict__ out)
{
    extern __shared__ __align__(16) float sm[];
    const int bid = blockIdx.x;
    if (bid >= d_num_ctas) return;

    const int expert = d_cta_expert[bid];
    const int nbase  = d_cta_base[bid];
    const int nm     = d_cta_cnt[bid];

    const int tid  = threadIdx.x;
    const int warp = tid >> 5;
    const int lane = tid & 31;
    const int g    = lane >> 2;
    const int tig  = lane & 3;
    const int wm   = warp & 1;       // 0..1 : e-half
    const int wn   = warp >> 1;      // 0..3 : row-quarter

    // per-node x base pointers
    const float* pxn[NPB];
    #pragma unroll
    for (int s = 0; s < NPB; ++s) {
        int node = (s < nm) ? d_perm[nbase + s] : d_perm[nbase];
        pxn[s] = x + (size_t)node * (T_HIST * D_SKIP);
    }

    // ---- W1 cp.async setup ----
    const int pe = tid >> 3;      // 0..31 (row group base)
    const int pk = tid & 7;       // 0..7  (16B quad)
    const float* w1src = d_w1tf + (size_t)expert * (E_END * D_SKIP) + pk * 4;  // + row*256 + c*32
    const uint32_t w1s_saddr = (uint32_t)__cvta_generic_to_shared(sm + W1S_OFF) + pk * 16;

    // prologue: chunk 0 -> buf 0
    #pragma unroll
    for (int j = 0; j < 4; ++j) {
        const int row = pe + 32 * j;
        cp16(w1s_saddr + row * (W1S_STRIDE * 4), w1src + row * D_SKIP);
    }
    asm volatile("cp.async.commit_group;");

    // ---- mainloop: D[e][row] = sum_k W1[e][k]*relu(x)[row][k] (tf32 mma) ----
    float acc[4][4][4];
    #pragma unroll
    for (int mt = 0; mt < 4; ++mt)
        #pragma unroll
        for (int nt = 0; nt < 4; ++nt)
            #pragma unroll
            for (int i = 0; i < 4; ++i) acc[mt][nt][i] = 0.f;

    #pragma unroll 1
    for (int c = 0; c < 8; ++c) {
        const int buf = c & 1;
        if ((c & 3) == 0) {
            __syncthreads();   // xs region free: mma of previous half fully done
            const int kbase = (c >> 2) * 128;
            #pragma unroll 1
            for (int s = 0; s < nm; ++s) {
                const float* xg = pxn[s] + kbase;
                #pragma unroll
                for (int i = tid; i < T_HIST * 32; i += NTHREADS) {
                    int t  = i >> 5;
                    int kq = i & 31;
                    float4 v = *(const float4*)(xg + t * D_SKIP + kq * 4);
                    v.x = tf32_rna(fmaxf(v.x, 0.f));
                    v.y = tf32_rna(fmaxf(v.y, 0.f));
                    v.z = tf32_rna(fmaxf(v.z, 0.f));
                    v.w = tf32_rna(fmaxf(v.w, 0.f));
                    *(float4*)(sm + XS_OFF + (s * T_HIST + t) * XS_STRIDE + kq * 4) = v;
                }
            }
        }

        // wait for chunk c's w1s data (only pending group), then barrier.
        // The barrier ALSO guarantees every thread finished mma(c-1) (program order),
        // so buf (c+1)&1 — read by mma(c-1) — is safe to overwrite right after it.
        asm volatile("cp.async.wait_group 0;");
        __syncthreads();

        if (c < 7) {
            const int nb = (c + 1) & 1;
            const float* src = w1src + (c + 1) * 32;
            const uint32_t dst = w1s_saddr + nb * (W1S_BUF * 4);
            #pragma unroll
            for (int j = 0; j < 4; ++j) {
                const int row = pe + 32 * j;
                cp16(dst + row * (W1S_STRIDE * 4), src + row * D_SKIP);
            }
            asm volatile("cp.async.commit_group;");
        }

        const float* w1b = sm + W1S_OFF + buf * W1S_BUF;
        #pragma unroll
        for (int kt = 0; kt < 4; ++kt) {
            const int kb = kt * 8;                 // k within chunk (w1s)
            const int xk = (c & 3) * 32 + kb;      // k within half (xs)
            unsigned a[4][4];
            #pragma unroll
            for (int mt = 0; mt < 4; ++mt) {
                const int e0 = wm * 64 + mt * 16 + g;
                a[mt][0] = __float_as_uint(w1b[e0 * W1S_STRIDE + kb + tig]);
                a[mt][1] = __float_as_uint(w1b[(e0 + 8) * W1S_STRIDE + kb + tig]);
                a[mt][2] = __float_as_uint(w1b[e0 * W1S_STRIDE + kb + tig + 4]);
                a[mt][3] = __float_as_uint(w1b[(e0 + 8) * W1S_STRIDE + kb + tig + 4]);
            }
            #pragma unroll
            for (int nt = 0; nt < 4; ++nt) {
                const int col = wn * 32 + nt * 8 + g;   // row index
                unsigned b0  = __float_as_uint(sm[XS_OFF + col * XS_STRIDE + xk + tig]);
                unsigned b1v = __float_as_uint(sm[XS_OFF + col * XS_STRIDE + xk + tig + 4]);
                #pragma unroll
                for (int mt = 0; mt < 4; ++mt)
                    mma_tf32(acc[mt][nt], a[mt], b0, b1v);
            }
        }
    }

    __syncthreads();   // all xs/w1s reads done -> reuse as hs[row][e]

    // ---- stage-2 weights: contiguous copy from pre-transposed d_w2t ----
    {
        const float* w2g = d_w2t + expert * (KW * OUT_DIM * E_END);
        #pragma unroll
        for (int i = tid; i < KW * OUT_DIM * E_END; i += NTHREADS)
            sm[W2S_OFF + (i >> 8) * W2S_STRIDE + (i & 255)] = w2g[i];
    }

    // ---- epilogue: hs[row][e] = relu(D[e][row] + b1[e]) ----
    const float* b1g = b1 + expert * E_END;
    const int maxrow = nm * T_HIST;
    #pragma unroll
    for (int mt = 0; mt < 4; ++mt) {
        const int eA = wm * 64 + mt * 16 + g;
        const int eB = eA + 8;
        const float bA = b1g[eA];
        const float bB = b1g[eB];
        #pragma unroll
        for (int nt = 0; nt < 4; ++nt) {
            const int row0 = wn * 32 + nt * 8 + 2 * tig;
            if (row0 < maxrow) {
                sm[HS_OFF + row0 * HS_STRIDE + eA] = fmaxf(acc[mt][nt][0] + bA, 0.f);
                sm[HS_OFF + row0 * HS_STRIDE + eB] = fmaxf(acc[mt][nt][2] + bB, 0.f);
            }
            const int row1 = row0 + 1;
            if (row1 < maxrow) {
                sm[HS_OFF + row1 * HS_STRIDE + eA] = fmaxf(acc[mt][nt][1] + bA, 0.f);
                sm[HS_OFF + row1 * HS_STRIDE + eB] = fmaxf(acc[mt][nt][3] + bB, 0.f);
            }
        }
    }
    __syncthreads();

    // ---- stage 2: per-node temporal conv, register resident ----
    #pragma unroll 1
    for (int iter = 0; iter < 3; ++iter) {
        const int wj   = iter * 8 + warp;
        const int node = wj >> 2;
        const int w4   = wj & 3;
        if (node < nm) {
            const int e = w4 * 32 + lane;
            float w2r[OUT_DIM][KW];
            #pragma unroll
            for (int o = 0; o < OUT_DIM; ++o)
                #pragma unroll
                for (int kk = 0; kk < KW; ++kk)
                    w2r[o][kk] = sm[W2S_OFF + kk * W2S_STRIDE + o * E_END + e];

            float a2[F_STEPS][OUT_DIM];
            #pragma unroll
            for (int f = 0; f < F_STEPS; ++f) { a2[f][0] = 0.f; a2[f][1] = 0.f; }

            const float* hsp = sm + HS_OFF + node * T_HIST * HS_STRIDE + e;
            #pragma unroll
            for (int t = 0; t < T_HIST; ++t) {
                const float hv = hsp[t * HS_STRIDE];
                #pragma unroll
                for (int kk = 0; kk < KW; ++kk) {
                    const int f = t - kk;
                    if (f >= 0 && f < F_STEPS) {
                        a2[f][0] = fmaf(hv, w2r[0][kk], a2[f][0]);
                        a2[f][1] = fmaf(hv, w2r[1][kk], a2[f][1]);
                    }
                }
            }
            #pragma unroll
            for (int f = 0; f < F_STEPS; ++f)
                #pragma unroll
                for (int o = 0; o < OUT_DIM; ++o) {
                    float v = a2[f][o];
                    v += __shfl_xor_sync(0xffffffffu, v, 16);
                    v += __shfl_xor_sync(0xffffffffu, v, 8);
                    v += __shfl_xor_sync(0xffffffffu, v, 4);
                    v += __shfl_xor_sync(0xffffffffu, v, 2);
                    v += __shfl_xor_sync(0xffffffffu, v, 1);
                    a2[f][o] = v;
                }
            if (lane == 0) {
                #pragma unroll
                for (int f = 0; f < F_STEPS; ++f) {
                    sm[RED_OFF + (node * 4 + w4) * 24 + f * 2 + 0] = a2[f][0];
                    sm[RED_OFF + (node * 4 + w4) * 24 + f * 2 + 1] = a2[f][1];
                }
            }
        }
    }
    __syncthreads();

    if (tid < nm * (F_STEPS * OUT_DIM)) {
        const int node = tid / 24;
        const int fo   = tid - node * 24;
        float ssum = sm[RED_OFF + (node * 4 + 0) * 24 + fo]
                   + sm[RED_OFF + (node * 4 + 1) * 24 + fo]
                   + sm[RED_OFF + (node * 4 + 2) * 24 + fo]
                   + sm[RED_OFF + (node * 4 + 3) * 24 + fo];
        ssum += b2[expert * OUT_DIM + (fo & 1)];
        out[(size_t)d_perm[nbase + node] * (F_STEPS * OUT_DIM) + fo] = ssum;
    }
}

extern "C" void kernel_launch(void* const* d_in, const int* in_sizes, int n_in,
                              void* d_out, int out_size) {
    const float* x      = (const float*)d_in[0];
    const int*   labels = (const int*)d_in[1];
    const float* W1     = (const float*)d_in[2];
    const float* b1     = (const float*)d_in[3];
    const float* W2     = (const float*)d_in[4];
    const float* b2     = (const float*)d_in[5];
    float* out = (float*)d_out;

    static bool attr_set = false;
    if (!attr_set) {
        cudaFuncSetAttribute(tcnn_grouped_kernel,
                             cudaFuncAttributeMaxDynamicSharedMemorySize, SMEM_BYTES);
        attr_set = true;
    }

    setup_kernel<<<257, NTHREADS>>>(labels, W1, W2);
    tcnn_grouped_kernel<<<MAXCTA, NTHREADS, SMEM_BYTES>>>(x, b1, b2, out);
}

// round 11
// speedup vs baseline: 1.3174x; 1.0118x over previous
#include <cuda_runtime.h>
#include <cstdint>

// ---- problem constants ----
#define NODES     4096
#define T_HIST    24
#define D_SKIP    256
#define E_END     128
#define KW        13
#define F_STEPS   12
#define OUT_DIM   2
#define NPB       5
#define NTHREADS  256
#define MAXCTA    832

// ---- smem layout (floats), occupancy-2 budget ----
// mainloop: xs [128][132] @0 (one 128-k half), w1s 2 bufs x [128][36] @16896 (ends 26112)
// stage 2 : hs [120][128] @0 (ends 15360), w2s [13][257] @15360 (ends 18701), red @18701
#define XS_OFF     0
#define XS_STRIDE  132
#define W1S_OFF    16896
#define W1S_BUF    4608
#define W1S_STRIDE 36
#define HS_OFF     0
#define HS_STRIDE  128
#define W2S_OFF    15360
#define W2S_STRIDE 257
#define RED_OFF    18701
#define SMEM_FLOATS 26112
#define SMEM_BYTES  (SMEM_FLOATS * 4)

// ---- device scratch ----
__device__ int d_perm[NODES];
__device__ int d_cta_expert[MAXCTA];
__device__ int d_cta_base[MAXCTA];
__device__ int d_cta_cnt[MAXCTA];
__device__ int d_num_ctas;
__device__ float d_w1tf[8 * E_END * D_SKIP];      // tf32-preconverted W1
__device__ float d_w2t[8 * KW * OUT_DIM * E_END]; // W2 transposed to [e][kk][o*128+en]

__device__ __forceinline__ float tf32_rna(float x) {
    unsigned u;
    asm("cvt.rna.tf32.f32 %0, %1;" : "=r"(u) : "f"(x));
    return __uint_as_float(u);
}

__device__ __forceinline__ void mma_tf32(float (&d)[4], const unsigned (&a)[4],
                                         unsigned b0, unsigned b1) {
    asm volatile(
        "mma.sync.aligned.m16n8k8.row.col.f32.tf32.tf32.f32 "
        "{%0,%1,%2,%3}, {%4,%5,%6,%7}, {%8,%9}, {%0,%1,%2,%3};"
        : "+f"(d[0]), "+f"(d[1]), "+f"(d[2]), "+f"(d[3])
        : "r"(a[0]), "r"(a[1]), "r"(a[2]), "r"(a[3]), "r"(b0), "r"(b1));
}

// ================= setup: block 0 = prepass, blocks 1.. = weight convert =================
__global__ void setup_kernel(const int* __restrict__ labels,
                             const float* __restrict__ W1,
                             const float* __restrict__ W2) {
    if (blockIdx.x == 0) {
        __shared__ int cnt[8], off[8], pos[8], blkoff[9], total_s;
        const int tid = threadIdx.x;
        const int lane = tid & 31;
        if (tid < 8) { cnt[tid] = 0; pos[tid] = 0; }
        __syncthreads();
        for (int i = tid; i < NODES; i += NTHREADS) {
            int l = labels[i];
            unsigned mask = __match_any_sync(0xffffffffu, l);
            int leader = __ffs(mask) - 1;
            if (lane == leader) atomicAdd(&cnt[l], __popc(mask));
        }
        __syncthreads();
        if (tid == 0) {
            int acc = 0, bacc = 0;
            for (int e = 0; e < 8; ++e) {
                off[e] = acc;
                blkoff[e] = bacc;
                acc += cnt[e];
                bacc += (cnt[e] + NPB - 1) / NPB;
            }
            blkoff[8] = bacc;
            total_s = bacc;
            d_num_ctas = bacc;
        }
        __syncthreads();
        for (int i = tid; i < NODES; i += NTHREADS) {
            int l = labels[i];
            unsigned mask = __match_any_sync(0xffffffffu, l);
            int leader = __ffs(mask) - 1;
            int rank = __popc(mask & ((1u << lane) - 1u));
            int basep = 0;
            if (lane == leader) basep = atomicAdd(&pos[l], __popc(mask));
            basep = __shfl_sync(0xffffffffu, basep, leader);
            d_perm[off[l] + basep + rank] = i;
        }
        const int total = total_s;
        for (int i = tid; i < total; i += NTHREADS) {
            int e = 0;
            while (blkoff[e + 1] <= i) ++e;
            int j = i - blkoff[e];
            int rem = cnt[e] - j * NPB;
            d_cta_expert[i] = e;
            d_cta_base[i]   = off[e] + j * NPB;
            d_cta_cnt[i]    = rem < NPB ? rem : NPB;
        }
    } else {
        const int idx = (blockIdx.x - 1) * NTHREADS + threadIdx.x;
        const int stride = (gridDim.x - 1) * NTHREADS;
        for (int i = idx; i < 8 * E_END * D_SKIP; i += stride)
            d_w1tf[i] = tf32_rna(W1[i]);
        for (int i = idx; i < 8 * KW * OUT_DIM * E_END; i += stride) {
            int e  = i / (KW * OUT_DIM * E_END);
            int r  = i - e * (KW * OUT_DIM * E_END);
            int kk = r >> 8;
            int oe = r & 255;
            int o  = oe >> 7;
            int en = oe & 127;
            d_w2t[i] = W2[((e * OUT_DIM + o) * E_END + en) * KW + kk];
        }
    }
}

// ================= main kernel =================
__global__ void __launch_bounds__(NTHREADS, 2)
tcnn_grouped_kernel(const float* __restrict__ x,
                    const float* __restrict__ b1,
                    const float* __restrict__ b2,
                    float* __restrict__ out)
{
    extern __shared__ __align__(16) float sm[];
    const int bid = blockIdx.x;
    if (bid >= d_num_ctas) return;

    const int expert = d_cta_expert[bid];
    const int nbase  = d_cta_base[bid];
    const int nm     = d_cta_cnt[bid];

    const int tid  = threadIdx.x;
    const int warp = tid >> 5;
    const int lane = tid & 31;
    const int g    = lane >> 2;
    const int tig  = lane & 3;
    const int wm   = warp & 1;       // 0..1 : e-half
    const int wn   = warp >> 1;      // 0..3 : row-quarter

    // per-node x base pointers
    const float* pxn[NPB];
    #pragma unroll
    for (int s = 0; s < NPB; ++s) {
        int node = (s < nm) ? d_perm[nbase + s] : d_perm[nbase];
        pxn[s] = x + (size_t)node * (T_HIST * D_SKIP);
    }

    // ---- W1 prefetch setup (register double-buffer, pre-converted tf32) ----
    const int pe = tid >> 3;      // 0..31 (row group base)
    const int pk = tid & 7;       // 0..7  (16B quad)
    const float* w1src = d_w1tf + (size_t)expert * (E_END * D_SKIP) + pk * 4;  // + row*256 + c*32
    float* w1dst = sm + W1S_OFF + pk * 4;                                       // + buf*W1S_BUF + row*36

    // prologue: prefetch chunk 0 into registers
    float4 pre[4];
    #pragma unroll
    for (int j = 0; j < 4; ++j)
        pre[j] = *(const float4*)(w1src + (pe + 32 * j) * D_SKIP);

    // ---- mainloop: D[e][row] = sum_k W1[e][k]*relu(x)[row][k] (tf32 mma) ----
    float acc[4][4][4];
    #pragma unroll
    for (int mt = 0; mt < 4; ++mt)
        #pragma unroll
        for (int nt = 0; nt < 4; ++nt)
            #pragma unroll
            for (int i = 0; i < 4; ++i) acc[mt][nt][i] = 0.f;

    #pragma unroll 1
    for (int c = 0; c < 8; ++c) {
        const int buf = c & 1;
        if ((c & 3) == 0) {
            __syncthreads();   // xs region free: mma of previous half fully done
            const int kbase = (c >> 2) * 128;
            #pragma unroll 1
            for (int s = 0; s < nm; ++s) {
                const float* xg = pxn[s] + kbase;
                #pragma unroll
                for (int i = tid; i < T_HIST * 32; i += NTHREADS) {
                    int t  = i >> 5;
                    int kq = i & 31;
                    float4 v = *(const float4*)(xg + t * D_SKIP + kq * 4);
                    v.x = tf32_rna(fmaxf(v.x, 0.f));
                    v.y = tf32_rna(fmaxf(v.y, 0.f));
                    v.z = tf32_rna(fmaxf(v.z, 0.f));
                    v.w = tf32_rna(fmaxf(v.w, 0.f));
                    *(float4*)(sm + XS_OFF + (s * T_HIST + t) * XS_STRIDE + kq * 4) = v;
                }
            }
        }

        // STS prefetched chunk c into buf (safe: concurrent warps' mma(c-1) reads
        // the OTHER buffer; mma(c-2) readers of this buffer passed barrier c-1)
        {
            float* dst = w1dst + buf * W1S_BUF;
            #pragma unroll
            for (int j = 0; j < 4; ++j)
                *(float4*)(dst + (pe + 32 * j) * W1S_STRIDE) = pre[j];
        }
        // prefetch chunk c+1 into registers (full chunk of latency slack)
        if (c < 7) {
            const float* src = w1src + (c + 1) * 32;
            #pragma unroll
            for (int j = 0; j < 4; ++j)
                pre[j] = *(const float4*)(src + (pe + 32 * j) * D_SKIP);
        }
        __syncthreads();       // chunk c's w1s + xs visible to all

        const float* w1b = sm + W1S_OFF + buf * W1S_BUF;
        #pragma unroll
        for (int kt = 0; kt < 4; ++kt) {
            const int kb = kt * 8;                 // k within chunk (w1s)
            const int xk = (c & 3) * 32 + kb;      // k within half (xs)
            unsigned a[4][4];
            #pragma unroll
            for (int mt = 0; mt < 4; ++mt) {
                const int e0 = wm * 64 + mt * 16 + g;
                a[mt][0] = __float_as_uint(w1b[e0 * W1S_STRIDE + kb + tig]);
                a[mt][1] = __float_as_uint(w1b[(e0 + 8) * W1S_STRIDE + kb + tig]);
                a[mt][2] = __float_as_uint(w1b[e0 * W1S_STRIDE + kb + tig + 4]);
                a[mt][3] = __float_as_uint(w1b[(e0 + 8) * W1S_STRIDE + kb + tig + 4]);
            }
            #pragma unroll
            for (int nt = 0; nt < 4; ++nt) {
                const int col = wn * 32 + nt * 8 + g;   // row index
                unsigned b0  = __float_as_uint(sm[XS_OFF + col * XS_STRIDE + xk + tig]);
                unsigned b1v = __float_as_uint(sm[XS_OFF + col * XS_STRIDE + xk + tig + 4]);
                #pragma unroll
                for (int mt = 0; mt < 4; ++mt)
                    mma_tf32(acc[mt][nt], a[mt], b0, b1v);
            }
        }
    }

    __syncthreads();   // all xs/w1s reads done -> reuse as hs[row][e]

    // ---- stage-2 weights: contiguous copy from pre-transposed d_w2t ----
    {
        const float* w2g = d_w2t + expert * (KW * OUT_DIM * E_END);
        #pragma unroll
        for (int i = tid; i < KW * OUT_DIM * E_END; i += NTHREADS)
            sm[W2S_OFF + (i >> 8) * W2S_STRIDE + (i & 255)] = w2g[i];
    }

    // ---- epilogue: hs[row][e] = relu(D[e][row] + b1[e]) ----
    const float* b1g = b1 + expert * E_END;
    const int maxrow = nm * T_HIST;
    #pragma unroll
    for (int mt = 0; mt < 4; ++mt) {
        const int eA = wm * 64 + mt * 16 + g;
        const int eB = eA + 8;
        const float bA = b1g[eA];
        const float bB = b1g[eB];
        #pragma unroll
        for (int nt = 0; nt < 4; ++nt) {
            const int row0 = wn * 32 + nt * 8 + 2 * tig;
            if (row0 < maxrow) {
                sm[HS_OFF + row0 * HS_STRIDE + eA] = fmaxf(acc[mt][nt][0] + bA, 0.f);
                sm[HS_OFF + row0 * HS_STRIDE + eB] = fmaxf(acc[mt][nt][2] + bB, 0.f);
            }
            const int row1 = row0 + 1;
            if (row1 < maxrow) {
                sm[HS_OFF + row1 * HS_STRIDE + eA] = fmaxf(acc[mt][nt][1] + bA, 0.f);
                sm[HS_OFF + row1 * HS_STRIDE + eB] = fmaxf(acc[mt][nt][3] + bB, 0.f);
            }
        }
    }
    __syncthreads();

    // ---- stage 2: per-node temporal conv, register resident ----
    #pragma unroll 1
    for (int iter = 0; iter < 3; ++iter) {
        const int wj   = iter * 8 + warp;
        const int node = wj >> 2;
        const int w4   = wj & 3;
        if (node < nm) {
            const int e = w4 * 32 + lane;
            float w2r[OUT_DIM][KW];
            #pragma unroll
            for (int o = 0; o < OUT_DIM; ++o)
                #pragma unroll
                for (int kk = 0; kk < KW; ++kk)
                    w2r[o][kk] = sm[W2S_OFF + kk * W2S_STRIDE + o * E_END + e];

            float a2[F_STEPS][OUT_DIM];
            #pragma unroll
            for (int f = 0; f < F_STEPS; ++f) { a2[f][0] = 0.f; a2[f][1] = 0.f; }

            const float* hsp = sm + HS_OFF + node * T_HIST * HS_STRIDE + e;
            #pragma unroll
            for (int t = 0; t < T_HIST; ++t) {
                const float hv = hsp[t * HS_STRIDE];
                #pragma unroll
                for (int kk = 0; kk < KW; ++kk) {
                    const int f = t - kk;
                    if (f >= 0 && f < F_STEPS) {
                        a2[f][0] = fmaf(hv, w2r[0][kk], a2[f][0]);
                        a2[f][1] = fmaf(hv, w2r[1][kk], a2[f][1]);
                    }
                }
            }
            #pragma unroll
            for (int f = 0; f < F_STEPS; ++f)
                #pragma unroll
                for (int o = 0; o < OUT_DIM; ++o) {
                    float v = a2[f][o];
                    v += __shfl_xor_sync(0xffffffffu, v, 16);
                    v += __shfl_xor_sync(0xffffffffu, v, 8);
                    v += __shfl_xor_sync(0xffffffffu, v, 4);
                    v += __shfl_xor_sync(0xffffffffu, v, 2);
                    v += __shfl_xor_sync(0xffffffffu, v, 1);
                    a2[f][o] = v;
                }
            if (lane == 0) {
                #pragma unroll
                for (int f = 0; f < F_STEPS; ++f) {
                    sm[RED_OFF + (node * 4 + w4) * 24 + f * 2 + 0] = a2[f][0];
                    sm[RED_OFF + (node * 4 + w4) * 24 + f * 2 + 1] = a2[f][1];
                }
            }
        }
    }
    __syncthreads();

    if (tid < nm * (F_STEPS * OUT_DIM)) {
        const int node = tid / 24;
        const int fo   = tid - node * 24;
        float ssum = sm[RED_OFF + (node * 4 + 0) * 24 + fo]
                   + sm[RED_OFF + (node * 4 + 1) * 24 + fo]
                   + sm[RED_OFF + (node * 4 + 2) * 24 + fo]
                   + sm[RED_OFF + (node * 4 + 3) * 24 + fo];
        ssum += b2[expert * OUT_DIM + (fo & 1)];
        out[(size_t)d_perm[nbase + node] * (F_STEPS * OUT_DIM) + fo] = ssum;
    }
}

extern "C" void kernel_launch(void* const* d_in, const int* in_sizes, int n_in,
                              void* d_out, int out_size) {
    const float* x      = (const float*)d_in[0];
    const int*   labels = (const int*)d_in[1];
    const float* W1     = (const float*)d_in[2];
    const float* b1     = (const float*)d_in[3];
    const float* W2     = (const float*)d_in[4];
    const float* b2     = (const float*)d_in[5];
    float* out = (float*)d_out;

    static bool attr_set = false;
    if (!attr_set) {
        cudaFuncSetAttribute(tcnn_grouped_kernel,
                             cudaFuncAttributeMaxDynamicSharedMemorySize, SMEM_BYTES);
        attr_set = true;
    }

    setup_kernel<<<257, NTHREADS>>>(labels, W1, W2);
    tcnn_grouped_kernel<<<MAXCTA, NTHREADS, SMEM_BYTES>>>(x, b1, b2, out);
}

// round 12
// speedup vs baseline: 1.5250x; 1.1575x over previous
#include <cuda_runtime.h>
#include <cstdint>

// ---- problem constants ----
#define NODES     4096
#define T_HIST    24
#define D_SKIP    256
#define E_END     128
#define KW        13
#define F_STEPS   12
#define OUT_DIM   2
#define NPB       5
#define NTHREADS  256
#define MAXCTA    832

// ---- smem layout (floats), occupancy-2 budget ----
// mainloop: xb 2 bufs x [128][68] @0 (raw f32 quarters, ends 17408)
//           w1s 2 bufs x [128][36] @17408 (ends 26624)
// stage 2 : hs [120][128] @0 (ends 15360), w2s [13][257] @15360 (ends 18701), red @18701
#define XB_OFF     0
#define XB_BUF     8704
#define XB_STRIDE  68
#define W1S_OFF    17408
#define W1S_BUF    4608
#define W1S_STRIDE 36
#define HS_OFF     0
#define HS_STRIDE  128
#define W2S_OFF    15360
#define W2S_STRIDE 257
#define RED_OFF    18701
#define SMEM_FLOATS 26624
#define SMEM_BYTES  (SMEM_FLOATS * 4)

// ---- device scratch ----
__device__ int d_perm[NODES];
__device__ int d_cta_expert[MAXCTA];
__device__ int d_cta_base[MAXCTA];
__device__ int d_cta_cnt[MAXCTA];
__device__ int d_num_ctas;
__device__ float d_w1tf[8 * E_END * D_SKIP];      // tf32-preconverted W1
__device__ float d_w2t[8 * KW * OUT_DIM * E_END]; // W2 transposed to [e][kk][o*128+en]

__device__ __forceinline__ float tf32_rna(float x) {
    unsigned u;
    asm("cvt.rna.tf32.f32 %0, %1;" : "=r"(u) : "f"(x));
    return __uint_as_float(u);
}
__device__ __forceinline__ unsigned tf32_relu_bits(float x) {
    unsigned u;
    float r = fmaxf(x, 0.f);
    asm("cvt.rna.tf32.f32 %0, %1;" : "=r"(u) : "f"(r));
    return u;
}
__device__ __forceinline__ void cp16(uint32_t dst, const float* src) {
    asm volatile("cp.async.ca.shared.global [%0], [%1], 16;" :: "r"(dst), "l"(src));
}

__device__ __forceinline__ void mma_tf32(float (&d)[4], const unsigned (&a)[4],
                                         unsigned b0, unsigned b1) {
    asm volatile(
        "mma.sync.aligned.m16n8k8.row.col.f32.tf32.tf32.f32 "
        "{%0,%1,%2,%3}, {%4,%5,%6,%7}, {%8,%9}, {%0,%1,%2,%3};"
        : "+f"(d[0]), "+f"(d[1]), "+f"(d[2]), "+f"(d[3])
        : "r"(a[0]), "r"(a[1]), "r"(a[2]), "r"(a[3]), "r"(b0), "r"(b1));
}

// ================= setup: block 0 = prepass, blocks 1.. = weight convert =================
__global__ void setup_kernel(const int* __restrict__ labels,
                             const float* __restrict__ W1,
                             const float* __restrict__ W2) {
    const int nt = blockDim.x;
    if (blockIdx.x == 0) {
        __shared__ int cnt[8], off[8], pos[8], blkoff[9], total_s;
        const int tid = threadIdx.x;
        const int lane = tid & 31;
        if (tid < 8) { cnt[tid] = 0; pos[tid] = 0; }
        __syncthreads();
        for (int i = tid; i < NODES; i += nt) {
            int l = labels[i];
            unsigned mask = __match_any_sync(0xffffffffu, l);
            int leader = __ffs(mask) - 1;
            if (lane == leader) atomicAdd(&cnt[l], __popc(mask));
        }
        __syncthreads();
        if (tid == 0) {
            int acc = 0, bacc = 0;
            for (int e = 0; e < 8; ++e) {
                off[e] = acc;
                blkoff[e] = bacc;
                acc += cnt[e];
                bacc += (cnt[e] + NPB - 1) / NPB;
            }
            blkoff[8] = bacc;
            total_s = bacc;
            d_num_ctas = bacc;
        }
        __syncthreads();
        for (int i = tid; i < NODES; i += nt) {
            int l = labels[i];
            unsigned mask = __match_any_sync(0xffffffffu, l);
            int leader = __ffs(mask) - 1;
            int rank = __popc(mask & ((1u << lane) - 1u));
            int basep = 0;
            if (lane == leader) basep = atomicAdd(&pos[l], __popc(mask));
            basep = __shfl_sync(0xffffffffu, basep, leader);
            d_perm[off[l] + basep + rank] = i;
        }
        const int total = total_s;
        for (int i = tid; i < total; i += nt) {
            int e = 0;
            while (blkoff[e + 1] <= i) ++e;
            int j = i - blkoff[e];
            int rem = cnt[e] - j * NPB;
            d_cta_expert[i] = e;
            d_cta_base[i]   = off[e] + j * NPB;
            d_cta_cnt[i]    = rem < NPB ? rem : NPB;
        }
    } else {
        const int idx = (blockIdx.x - 1) * nt + threadIdx.x;
        const int stride = (gridDim.x - 1) * nt;
        for (int i = idx; i < 8 * E_END * D_SKIP; i += stride)
            d_w1tf[i] = tf32_rna(W1[i]);
        for (int i = idx; i < 8 * KW * OUT_DIM * E_END; i += stride) {
            int e  = i / (KW * OUT_DIM * E_END);
            int r  = i - e * (KW * OUT_DIM * E_END);
            int kk = r >> 8;
            int oe = r & 255;
            int o  = oe >> 7;
            int en = oe & 127;
            d_w2t[i] = W2[((e * OUT_DIM + o) * E_END + en) * KW + kk];
        }
    }
}

// ================= main kernel =================
__global__ void __launch_bounds__(NTHREADS, 2)
tcnn_grouped_kernel(const float* __restrict__ x,
                    const float* __restrict__ b1,
                    const float* __restrict__ b2,
                    float* __restrict__ out)
{
    extern __shared__ __align__(16) float sm[];
    const int bid = blockIdx.x;
    if (bid >= d_num_ctas) return;

    const int expert = d_cta_expert[bid];
    const int nbase  = d_cta_base[bid];
    const int nm     = d_cta_cnt[bid];

    const int tid  = threadIdx.x;
    const int warp = tid >> 5;
    const int lane = tid & 31;
    const int g    = lane >> 2;
    const int tig  = lane & 3;
    const int wm   = warp & 1;       // 0..1 : e-half
    const int wn   = warp >> 1;      // 0..3 : row-quarter

    // per-node x base pointers
    const float* pxn[NPB];
    #pragma unroll
    for (int s = 0; s < NPB; ++s) {
        int node = (s < nm) ? d_perm[nbase + s] : d_perm[nbase];
        pxn[s] = x + (size_t)node * (T_HIST * D_SKIP);
    }

    const uint32_t smem_saddr = (uint32_t)__cvta_generic_to_shared(sm);
    const int xcount = nm * 384;      // cp16 ops per quarter (24t x 16q per node)

    // ---- issue xs quarter 0 into xbuf 0 ----
    {
        #pragma unroll 1
        for (int i = tid; i < xcount; i += NTHREADS) {
            int s = i / 384;
            int r = i - s * 384;
            int t = r >> 4;
            int qd = r & 15;
            cp16(smem_saddr + (((s * 24 + t) * XB_STRIDE + qd * 4) << 2),
                 pxn[s] + t * D_SKIP + qd * 4);
        }
        asm volatile("cp.async.commit_group;");
    }

    // ---- W1 prefetch setup (register double-buffer, pre-converted tf32) ----
    const int pe = tid >> 3;      // 0..31 (row group base)
    const int pk = tid & 7;       // 0..7  (16B quad)
    const float* w1src = d_w1tf + (size_t)expert * (E_END * D_SKIP) + pk * 4;  // + row*256 + c*32
    float* w1dst = sm + W1S_OFF + pk * 4;                                       // + buf*W1S_BUF + row*36

    float4 pre[4];
    #pragma unroll
    for (int j = 0; j < 4; ++j)
        pre[j] = *(const float4*)(w1src + (pe + 32 * j) * D_SKIP);

    // ---- mainloop: D[e][row] = sum_k W1[e][k]*relu(x)[row][k] (tf32 mma) ----
    float acc[4][4][4];
    #pragma unroll
    for (int mt = 0; mt < 4; ++mt)
        #pragma unroll
        for (int nt = 0; nt < 4; ++nt)
            #pragma unroll
            for (int i = 0; i < 4; ++i) acc[mt][nt][i] = 0.f;

    #pragma unroll 1
    for (int c = 0; c < 8; ++c) {
        const int buf = c & 1;

        if ((c & 1) == 0) {
            // this thread's copies for quarter c/2 have landed
            asm volatile("cp.async.wait_group 0;");
        }

        // STS prefetched W1 chunk c (safe: mma c-1 reads other buf; c-2 readers flushed)
        {
            float* dst = w1dst + buf * W1S_BUF;
            #pragma unroll
            for (int j = 0; j < 4; ++j)
                *(float4*)(dst + (pe + 32 * j) * W1S_STRIDE) = pre[j];
        }
        if (c < 7) {
            const float* src = w1src + (c + 1) * 32;
            #pragma unroll
            for (int j = 0; j < 4; ++j)
                pre[j] = *(const float4*)(src + (pe + 32 * j) * D_SKIP);
        }
        __syncthreads();   // w1s chunk c + xs quarter c/2 visible; prev mma done

        // issue xs quarter q+1 (post-barrier: quarter q-1 readers flushed)
        if ((c & 1) == 0 && c < 6) {
            const int qn = (c >> 1) + 1;
            const uint32_t dstb = smem_saddr + (qn & 1) * (XB_BUF * 4);
            const int kb4 = qn * 64;
            #pragma unroll 1
            for (int i = tid; i < xcount; i += NTHREADS) {
                int s = i / 384;
                int r = i - s * 384;
                int t = r >> 4;
                int qd = r & 15;
                cp16(dstb + (((s * 24 + t) * XB_STRIDE + qd * 4) << 2),
                     pxn[s] + kb4 + t * D_SKIP + qd * 4);
            }
            asm volatile("cp.async.commit_group;");
        }

        const float* w1b = sm + W1S_OFF + buf * W1S_BUF;
        const float* xb  = sm + XB_OFF + ((c >> 1) & 1) * XB_BUF;
        #pragma unroll
        for (int kt = 0; kt < 4; ++kt) {
            const int kb = kt * 8;                 // k within chunk (w1s)
            const int xk = (c & 1) * 32 + kb;      // k within quarter (xb)
            unsigned a[4][4];
            #pragma unroll
            for (int mt = 0; mt < 4; ++mt) {
                const int e0 = wm * 64 + mt * 16 + g;
                a[mt][0] = __float_as_uint(w1b[e0 * W1S_STRIDE + kb + tig]);
                a[mt][1] = __float_as_uint(w1b[(e0 + 8) * W1S_STRIDE + kb + tig]);
                a[mt][2] = __float_as_uint(w1b[e0 * W1S_STRIDE + kb + tig + 4]);
                a[mt][3] = __float_as_uint(w1b[(e0 + 8) * W1S_STRIDE + kb + tig + 4]);
            }
            #pragma unroll
            for (int nt = 0; nt < 4; ++nt) {
                const int col = wn * 32 + nt * 8 + g;   // row index
                unsigned b0  = tf32_relu_bits(xb[col * XB_STRIDE + xk + tig]);
                unsigned b1v = tf32_relu_bits(xb[col * XB_STRIDE + xk + tig + 4]);
                #pragma unroll
                for (int mt = 0; mt < 4; ++mt)
                    mma_tf32(acc[mt][nt], a[mt], b0, b1v);
            }
        }
    }

    __syncthreads();   // all xb/w1s reads done -> reuse as hs[row][e]

    // ---- stage-2 weights: contiguous copy from pre-transposed d_w2t ----
    {
        const float* w2g = d_w2t + expert * (KW * OUT_DIM * E_END);
        #pragma unroll
        for (int i = tid; i < KW * OUT_DIM * E_END; i += NTHREADS)
            sm[W2S_OFF + (i >> 8) * W2S_STRIDE + (i & 255)] = w2g[i];
    }

    // ---- epilogue: hs[row][e] = relu(D[e][row] + b1[e]) ----
    const float* b1g = b1 + expert * E_END;
    const int maxrow = nm * T_HIST;
    #pragma unroll
    for (int mt = 0; mt < 4; ++mt) {
        const int eA = wm * 64 + mt * 16 + g;
        const int eB = eA + 8;
        const float bA = b1g[eA];
        const float bB = b1g[eB];
        #pragma unroll
        for (int nt = 0; nt < 4; ++nt) {
            const int row0 = wn * 32 + nt * 8 + 2 * tig;
            if (row0 < maxrow) {
                sm[HS_OFF + row0 * HS_STRIDE + eA] = fmaxf(acc[mt][nt][0] + bA, 0.f);
                sm[HS_OFF + row0 * HS_STRIDE + eB] = fmaxf(acc[mt][nt][2] + bB, 0.f);
            }
            const int row1 = row0 + 1;
            if (row1 < maxrow) {
                sm[HS_OFF + row1 * HS_STRIDE + eA] = fmaxf(acc[mt][nt][1] + bA, 0.f);
                sm[HS_OFF + row1 * HS_STRIDE + eB] = fmaxf(acc[mt][nt][3] + bB, 0.f);
            }
        }
    }
    __syncthreads();

    // ---- stage 2: per-node temporal conv, register resident ----
    #pragma unroll 1
    for (int iter = 0; iter < 3; ++iter) {
        const int wj   = iter * 8 + warp;
        const int node = wj >> 2;
        const int w4   = wj & 3;
        if (node < nm) {
            const int e = w4 * 32 + lane;
            float w2r[OUT_DIM][KW];
            #pragma unroll
            for (int o = 0; o < OUT_DIM; ++o)
                #pragma unroll
                for (int kk = 0; kk < KW; ++kk)
                    w2r[o][kk] = sm[W2S_OFF + kk * W2S_STRIDE + o * E_END + e];

            float a2[F_STEPS][OUT_DIM];
            #pragma unroll
            for (int f = 0; f < F_STEPS; ++f) { a2[f][0] = 0.f; a2[f][1] = 0.f; }

            const float* hsp = sm + HS_OFF + node * T_HIST * HS_STRIDE + e;
            #pragma unroll
            for (int t = 0; t < T_HIST; ++t) {
                const float hv = hsp[t * HS_STRIDE];
                #pragma unroll
                for (int kk = 0; kk < KW; ++kk) {
                    const int f = t - kk;
                    if (f >= 0 && f < F_STEPS) {
                        a2[f][0] = fmaf(hv, w2r[0][kk], a2[f][0]);
                        a2[f][1] = fmaf(hv, w2r[1][kk], a2[f][1]);
                    }
                }
            }
            #pragma unroll
            for (int f = 0; f < F_STEPS; ++f)
                #pragma unroll
                for (int o = 0; o < OUT_DIM; ++o) {
                    float v = a2[f][o];
                    v += __shfl_xor_sync(0xffffffffu, v, 16);
                    v += __shfl_xor_sync(0xffffffffu, v, 8);
                    v += __shfl_xor_sync(0xffffffffu, v, 4);
                    v += __shfl_xor_sync(0xffffffffu, v, 2);
                    v += __shfl_xor_sync(0xffffffffu, v, 1);
                    a2[f][o] = v;
                }
            if (lane == 0) {
                #pragma unroll
                for (int f = 0; f < F_STEPS; ++f) {
                    sm[RED_OFF + (node * 4 + w4) * 24 + f * 2 + 0] = a2[f][0];
                    sm[RED_OFF + (node * 4 + w4) * 24 + f * 2 + 1] = a2[f][1];
                }
            }
        }
    }
    __syncthreads();

    if (tid < nm * (F_STEPS * OUT_DIM)) {
        const int node = tid / 24;
        const int fo   = tid - node * 24;
        float ssum = sm[RED_OFF + (node * 4 + 0) * 24 + fo]
                   + sm[RED_OFF + (node * 4 + 1) * 24 + fo]
                   + sm[RED_OFF + (node * 4 + 2) * 24 + fo]
                   + sm[RED_OFF + (node * 4 + 3) * 24 + fo];
        ssum += b2[expert * OUT_DIM + (fo & 1)];
        out[(size_t)d_perm[nbase + node] * (F_STEPS * OUT_DIM) + fo] = ssum;
    }
}

extern "C" void kernel_launch(void* const* d_in, const int* in_sizes, int n_in,
                              void* d_out, int out_size) {
    const float* x      = (const float*)d_in[0];
    const int*   labels = (const int*)d_in[1];
    const float* W1     = (const float*)d_in[2];
    const float* b1     = (const float*)d_in[3];
    const float* W2     = (const float*)d_in[4];
    const float* b2     = (const float*)d_in[5];
    float* out = (float*)d_out;

    static bool attr_set = false;
    if (!attr_set) {
        cudaFuncSetAttribute(tcnn_grouped_kernel,
                             cudaFuncAttributeMaxDynamicSharedMemorySize, SMEM_BYTES);
        attr_set = true;
    }

    setup_kernel<<<129, 512>>>(labels, W1, W2);
    tcnn_grouped_kernel<<<MAXCTA, NTHREADS, SMEM_BYTES>>>(x, b1, b2, out);
}